// round 5
// baseline (speedup 1.0000x reference)
#include <cuda_runtime.h>
#include <cuda_fp16.h>
#include <math.h>

// CGCNN on GB300. fp16 node tables, f32x2-packed MLPs, pipelined edge pass.

#define NN 100000
#define EE 1600000
#define BB 256
#define FN 35
#define FE 10

typedef unsigned long long u64t;

__device__ float g_h[NN * 64];
__device__ __half g_Tsh[NN * 128];
__device__ __half g_Tdh[NN * 128];
__device__ float g_agg[NN * 64];
__device__ float g_stats[128];
__device__ float g_scale[64];
__device__ float g_shift[64];
__device__ float g_pool[BB * 64];
__device__ float g_cnt[BB];

__device__ __forceinline__ float fsoftplus(float x) {
    return fmaxf(x, 0.f) + __logf(1.f + __expf(-fabsf(x)));
}
__device__ __forceinline__ float fsigmoid(float x) {
    return __fdividef(1.f, 1.f + __expf(-x));
}
__device__ __forceinline__ u64t pack2(float lo, float hi) {
    u64t r;
    asm("mov.b64 %0, {%1, %2};" : "=l"(r) : "f"(lo), "f"(hi));
    return r;
}
__device__ __forceinline__ void unpack2(u64t v, float& lo, float& hi) {
    asm("mov.b64 {%0, %1}, %2;" : "=f"(lo), "=f"(hi) : "l"(v));
}
__device__ __forceinline__ u64t fma2(u64t a, u64t b, u64t c) {
    u64t r;
    asm("fma.rn.f32x2 %0, %1, %2, %3;" : "=l"(r) : "l"(a), "l"(b), "l"(c));
    return r;
}
__device__ __forceinline__ u64t add2(u64t a, u64t b) {
    u64t r;
    asm("add.rn.f32x2 %0, %1, %2;" : "=l"(r) : "l"(a), "l"(b));
    return r;
}
__device__ __forceinline__ void red_add_v4(float* p, float a, float b, float c, float d) {
    asm volatile("red.global.add.v4.f32 [%0], {%1, %2, %3, %4};"
                 :: "l"(p), "f"(a), "f"(b), "f"(c), "f"(d) : "memory");
}
__device__ __forceinline__ void red_add_f(float* p, float v) {
    asm volatile("red.global.add.f32 [%0], %1;" :: "l"(p), "f"(v) : "memory");
}

// ---------------- embed: h = nf @ ew + eb, 32 nodes/block ----------------
__global__ __launch_bounds__(256) void embed_k(const float* __restrict__ nf,
                                               const float* __restrict__ ew,
                                               const float* __restrict__ eb) {
    __shared__ float sw[FN * 64];
    __shared__ float sb[64];
    __shared__ float snf[32][FN + 1];
    int tid = threadIdx.x;
    for (int i = tid; i < FN * 64; i += 256) sw[i] = ew[i];
    if (tid < 64) sb[tid] = eb[tid];
    int n0 = blockIdx.x * 32;
    for (int i = tid; i < 32 * FN; i += 256) {
        int r = i / FN, c = i % FN;
        int n = n0 + r;
        snf[r][c] = (n < NN) ? nf[(size_t)n * FN + c] : 0.f;
    }
    __syncthreads();
    int r = tid >> 6, j = tid & 63;
#pragma unroll
    for (int ii = 0; ii < 8; ii++) {
        int rr = r + ii * 4;
        int n = n0 + rr;
        if (n < NN) {
            float acc = sb[j];
#pragma unroll
            for (int k = 0; k < FN; k++) acc = fmaf(snf[rr][k], sw[k * 64 + j], acc);
            g_h[(size_t)n * 64 + j] = acc;
        }
    }
}

// ---------------- node transform -> fp16 tables, f32x2 packed ----------------
// 128 threads; thread t owns (Ts col t, Td col t); weights packed {wTs, wTd}.
// h tile duplicated in smem so ld.shared.v4 yields two f32x2 splats.
__global__ __launch_bounds__(128) void nodetf_k(
    const float* __restrict__ gw, const float* __restrict__ cw,
    const float* __restrict__ gb, const float* __restrict__ cb) {
    __shared__ float2 hd[64 * 64];  // [node j][feat k] = {h, h}
    int t = threadIdx.x;
    const float* wbase;
    int cc;
    float biasB;
    if (t < 64) { wbase = gw; cc = t;      biasB = gb[t]; }
    else        { wbase = cw; cc = t - 64; biasB = cb[t - 64]; }
    u64t w2[64];
#pragma unroll
    for (int k = 0; k < 64; k++)
        w2[k] = pack2(wbase[k * 64 + cc], wbase[(64 + k) * 64 + cc]);
    u64t binit = pack2(0.f, biasB);

    int n0 = blockIdx.x * 64;
    // load + duplicate h tile: 1024 float4 / 128 threads = 8 iters
#pragma unroll
    for (int i = 0; i < 8; i++) {
        int idx = t + i * 128;
        int n = n0 + (idx >> 4);
        float4 v = (n < NN) ? ((const float4*)g_h)[(size_t)n0 * 16 + idx]
                            : make_float4(0.f, 0.f, 0.f, 0.f);
        int j = idx >> 4, kb = (idx & 15) * 4;
        float2* p = hd + j * 64 + kb;
        p[0] = make_float2(v.x, v.x);
        p[1] = make_float2(v.y, v.y);
        p[2] = make_float2(v.z, v.z);
        p[3] = make_float2(v.w, v.w);
    }
    __syncthreads();

#pragma unroll 1
    for (int j0 = 0; j0 < 64; j0 += 4) {
        u64t acc[4];
#pragma unroll
        for (int j = 0; j < 4; j++) acc[j] = binit;
#pragma unroll
        for (int k0 = 0; k0 < 64; k0 += 2) {
#pragma unroll
            for (int j = 0; j < 4; j++) {
                ulonglong2 hp = *(const ulonglong2*)(hd + (j0 + j) * 64 + k0);
                acc[j] = fma2(hp.x, w2[k0], acc[j]);
                acc[j] = fma2(hp.y, w2[k0 + 1], acc[j]);
            }
        }
#pragma unroll
        for (int j = 0; j < 4; j++) {
            int n = n0 + j0 + j;
            if (n < NN) {
                float a, b;
                unpack2(acc[j], a, b);
                g_Tsh[(size_t)n * 128 + t] = __float2half(a);
                g_Tdh[(size_t)n * 128 + t] = __float2half(b);
            }
        }
    }
}

// ---------------- zero kernels ----------------
__global__ void zero_agg_k() {
    int i = blockIdx.x * 256 + threadIdx.x;
    if (i < NN * 16) ((float4*)g_agg)[i] = make_float4(0.f, 0.f, 0.f, 0.f);
    if (i < 128) g_stats[i] = 0.f;
}
__global__ void zero_pool_k() {
    int i = blockIdx.x * 256 + threadIdx.x;
    if (i < BB * 64) g_pool[i] = 0.f;
    if (i < BB) g_cnt[i] = 0.f;
}

// ---------------- edge pass: warp/edge, f32x2 MLP, pipelined loads ----------------
#define EPW 16  // edges per warp; block = 8 warps = 128 edges
__global__ __launch_bounds__(256, 3) void edge_k(
    const int* __restrict__ src, const int* __restrict__ dst,
    const float* __restrict__ ef,
    const float* __restrict__ gwE, const float* __restrict__ cwE) {
    int tid = threadIdx.x;
    int warp = tid >> 5;
    int l = tid & 31;

    u64t wg[FE], wc[FE];
#pragma unroll
    for (int k = 0; k < FE; k++) {
        wg[k] = *(const u64t*)(gwE + k * 64 + 2 * l);
        wc[k] = *(const u64t*)(cwE + k * 64 + 2 * l);
    }

    int base = blockIdx.x * (8 * EPW) + warp * EPW;

    // prologue loads for edge 0
    int e = base;
    int s = __ldcs(&src[e]);
    int d = __ldcs(&dst[e]);
    const __half2* ts = (const __half2*)(g_Tsh + (size_t)s * 128);
    const __half2* td = (const __half2*)(g_Tdh + (size_t)d * 128);
    __half2 sg = ts[l], sc = ts[32 + l], dg = td[l], dc = td[32 + l];
    float ev = (l < FE) ? __ldcs(&ef[(size_t)e * FE + l]) : 0.f;

#pragma unroll 1
    for (int it = 0; it < EPW; it++) {
        // issue next edge's loads before compute/atomic
        int sn = 0, dn = 0;
        __half2 sgn, scn, dgn, dcn;
        float evn = 0.f;
        if (it < EPW - 1) {
            int en = e + 1;
            sn = __ldcs(&src[en]);
            dn = __ldcs(&dst[en]);
            const __half2* tsn = (const __half2*)(g_Tsh + (size_t)sn * 128);
            const __half2* tdn = (const __half2*)(g_Tdh + (size_t)dn * 128);
            sgn = tsn[l]; scn = tsn[32 + l]; dgn = tdn[l]; dcn = tdn[32 + l];
            evn = (l < FE) ? __ldcs(&ef[(size_t)en * FE + l]) : 0.f;
        }

        float2 a = __half22float2(sg), b = __half22float2(dg);
        float2 u = __half22float2(sc), v = __half22float2(dc);
        u64t x = add2(pack2(a.x, a.y), pack2(b.x, b.y));
        u64t y = add2(pack2(u.x, u.y), pack2(v.x, v.y));
#pragma unroll
        for (int k = 0; k < FE; k++) {
            float evk = __shfl_sync(0xffffffffu, ev, k);
            u64t ep = pack2(evk, evk);
            x = fma2(ep, wg[k], x);
            y = fma2(ep, wc[k], y);
        }
        float x0, x1, y0, y1;
        unpack2(x, x0, x1);
        unpack2(y, y0, y1);
        float m0 = fsigmoid(x0) * fsoftplus(y0);
        float m1 = fsigmoid(x1) * fsoftplus(y1);
        float p0 = __shfl_down_sync(0xffffffffu, m0, 1);
        float p1 = __shfl_down_sync(0xffffffffu, m1, 1);
        if ((l & 1) == 0)
            red_add_v4(g_agg + (size_t)s * 64 + 2 * l, m0, m1, p0, p1);

        e++;
        s = sn; d = dn;
        sg = sgn; sc = scn; dg = dgn; dc = dcn;
        ev = evn;
    }
}

// ---------------- BN stats ----------------
__global__ void stats_k() {
    int tid = threadIdx.x;
    int j = tid & 63;
    int r = tid >> 6;
    float s = 0.f, s2 = 0.f;
    for (int n = blockIdx.x * 4 + r; n < NN; n += gridDim.x * 4) {
        float v = g_agg[n * 64 + j];
        s += v;
        s2 += v * v;
    }
    __shared__ float sh[256], sh2[256];
    sh[tid] = s; sh2[tid] = s2;
    __syncthreads();
    if (tid < 64) {
        s = sh[tid] + sh[tid + 64] + sh[tid + 128] + sh[tid + 192];
        s2 = sh2[tid] + sh2[tid + 64] + sh2[tid + 128] + sh2[tid + 192];
        atomicAdd(&g_stats[tid], s);
        atomicAdd(&g_stats[64 + tid], s2);
    }
}

__global__ void bnfin_k(const float* __restrict__ bg, const float* __restrict__ bb) {
    int j = threadIdx.x;
    float mean = g_stats[j] * (1.f / NN);
    float var = g_stats[64 + j] * (1.f / NN) - mean * mean;
    float sc = bg[j] * rsqrtf(fmaxf(var, 0.f) + 1e-5f);
    g_scale[j] = sc;
    g_shift[j] = bb[j] - mean * sc;
}

// ---------------- h = softplus(h + agg*scale + shift) ----------------
__global__ void upd_k() {
    int i = blockIdx.x * 256 + threadIdx.x;
    if (i >= NN * 16) return;
    int j4 = (i & 15) * 4;
    float4 a = ((const float4*)g_agg)[i];
    float4 h = ((const float4*)g_h)[i];
    float4 sc = *(const float4*)(g_scale + j4);
    float4 sf = *(const float4*)(g_shift + j4);
    h.x = fsoftplus(fmaf(a.x, sc.x, h.x + sf.x));
    h.y = fsoftplus(fmaf(a.y, sc.y, h.y + sf.y));
    h.z = fsoftplus(fmaf(a.z, sc.z, h.z + sf.z));
    h.w = fsoftplus(fmaf(a.w, sc.w, h.w + sf.w));
    ((float4*)g_h)[i] = h;
}

// ---------------- pooling ----------------
__global__ void pool_k(const int* __restrict__ gi) {
    int i = blockIdx.x * 256 + threadIdx.x;
    if (i >= NN * 16) return;
    int n = i >> 4;
    int q = i & 15;
    int g = gi[n];
    float4 v = ((const float4*)g_h)[i];
    red_add_v4(g_pool + g * 64 + 4 * q, v.x, v.y, v.z, v.w);
    if (q == 0) red_add_f(&g_cnt[g], 1.f);
}

// ---------------- final MLP, one block per graph ----------------
__global__ void mlp_k(const float* __restrict__ w1, const float* __restrict__ b1,
                      const float* __restrict__ w2, const float* __restrict__ b2,
                      const float* __restrict__ w3, const float* __restrict__ b3,
                      float* __restrict__ out) {
    int b = blockIdx.x;
    int t = threadIdx.x;  // 128 threads
    __shared__ float pm[64];
    __shared__ float s1[128];
    __shared__ float s2[64];
    __shared__ float red[128];
    if (t < 64) {
        float c = g_cnt[b];
        c = (c < 1.f) ? 1.f : c;
        pm[t] = g_pool[b * 64 + t] / c;
    }
    __syncthreads();
    float a = b1[t];
#pragma unroll
    for (int k = 0; k < 64; k++) a = fmaf(pm[k], w1[k * 128 + t], a);
    s1[t] = fsoftplus(a);
    __syncthreads();
    if (t < 64) {
        float a2 = b2[t];
#pragma unroll
        for (int k = 0; k < 128; k++) a2 = fmaf(s1[k], w2[k * 64 + t], a2);
        s2[t] = fsoftplus(a2);
    }
    __syncthreads();
    float p = (t < 64) ? s2[t] * w3[t] : 0.f;
    red[t] = p;
    __syncthreads();
#pragma unroll
    for (int off = 64; off > 0; off >>= 1) {
        if (t < off) red[t] += red[t + off];
        __syncthreads();
    }
    if (t == 0) out[b] = red[0] + b3[0];
}

extern "C" void kernel_launch(void* const* d_in, const int* in_sizes, int n_in,
                              void* d_out, int out_size) {
    const float* nf  = (const float*)d_in[0];
    const int*   ei  = (const int*)d_in[1];
    const float* ef  = (const float*)d_in[2];
    const int*   gi  = (const int*)d_in[3];
    const float* ew  = (const float*)d_in[4];
    const float* eb  = (const float*)d_in[5];
    const float* gw  = (const float*)d_in[6];
    const float* gb  = (const float*)d_in[7];
    const float* cw  = (const float*)d_in[8];
    const float* cb  = (const float*)d_in[9];
    const float* bng = (const float*)d_in[10];
    const float* bnb = (const float*)d_in[11];
    const float* w1  = (const float*)d_in[12];
    const float* b1  = (const float*)d_in[13];
    const float* w2  = (const float*)d_in[14];
    const float* b2  = (const float*)d_in[15];
    const float* w3  = (const float*)d_in[16];
    const float* b3  = (const float*)d_in[17];
    float* out = (float*)d_out;
    const int* srcI = ei;
    const int* dstI = ei + EE;

    embed_k<<<(NN + 31) / 32, 256>>>(nf, ew, eb);
    for (int i = 0; i < 3; i++) {
        const float* gwi = gw + i * 138 * 64;
        const float* cwi = cw + i * 138 * 64;
        nodetf_k<<<(NN + 63) / 64, 128>>>(gwi, cwi, gb + i * 64, cb + i * 64);
        zero_agg_k<<<(NN * 16 + 255) / 256, 256>>>();
        edge_k<<<EE / 128, 256>>>(srcI, dstI, ef, gwi + 128 * 64, cwi + 128 * 64);
        stats_k<<<512, 256>>>();
        bnfin_k<<<1, 64>>>(bng + i * 64, bnb + i * 64);
        upd_k<<<(NN * 16 + 255) / 256, 256>>>();
    }
    zero_pool_k<<<64, 256>>>();
    pool_k<<<(NN * 16 + 255) / 256, 256>>>(gi);
    mlp_k<<<BB, 128>>>(w1, b1, w2, b2, w3, b3, out);
}

// round 7
// speedup vs baseline: 1.2936x; 1.2936x over previous
#include <cuda_runtime.h>
#include <cuda_fp16.h>
#include <math.h>

// CGCNN on GB300. fp16 node tables + fp16 h copy, HFMA2 edge projection and
// node GEMM, fp32 residual/BN/atomics.

#define NN 100000
#define EE 1600000
#define BB 256
#define FN 35
#define FE 10

__device__ float g_h[NN * 64];
__device__ __half g_hh[NN * 64];
__device__ __half g_Tsh[NN * 128];
__device__ __half g_Tdh[NN * 128];
__device__ float g_agg[NN * 64];
__device__ float g_stats[128];
__device__ float g_scale[64];
__device__ float g_shift[64];
__device__ float g_pool[BB * 64];
__device__ float g_cnt[BB];

__device__ __forceinline__ float fsoftplus(float x) {
    return fmaxf(x, 0.f) + __logf(1.f + __expf(-fabsf(x)));
}
__device__ __forceinline__ float fsigmoid(float x) {
    return __fdividef(1.f, 1.f + __expf(-x));
}
__device__ __forceinline__ void red_add_v4(float* p, float a, float b, float c, float d) {
    asm volatile("red.global.add.v4.f32 [%0], {%1, %2, %3, %4};"
                 :: "l"(p), "f"(a), "f"(b), "f"(c), "f"(d) : "memory");
}
__device__ __forceinline__ void red_add_f(float* p, float v) {
    asm volatile("red.global.add.f32 [%0], %1;" :: "l"(p), "f"(v) : "memory");
}

// ---------------- embed: h = nf @ ew + eb, 32 nodes/block ----------------
__global__ __launch_bounds__(256) void embed_k(const float* __restrict__ nf,
                                               const float* __restrict__ ew,
                                               const float* __restrict__ eb) {
    __shared__ float sw[FN * 64];
    __shared__ float sb[64];
    __shared__ float snf[32][FN + 1];
    int tid = threadIdx.x;
    for (int i = tid; i < FN * 64; i += 256) sw[i] = ew[i];
    if (tid < 64) sb[tid] = eb[tid];
    int n0 = blockIdx.x * 32;
    for (int i = tid; i < 32 * FN; i += 256) {
        int r = i / FN, c = i % FN;
        int n = n0 + r;
        snf[r][c] = (n < NN) ? nf[(size_t)n * FN + c] : 0.f;
    }
    __syncthreads();
    int r = tid >> 6, j = tid & 63;
#pragma unroll
    for (int ii = 0; ii < 8; ii++) {
        int rr = r + ii * 4;
        int n = n0 + rr;
        if (n < NN) {
            float acc = sb[j];
#pragma unroll
            for (int k = 0; k < FN; k++) acc = fmaf(snf[rr][k], sw[k * 64 + j], acc);
            g_h[(size_t)n * 64 + j] = acc;
            g_hh[(size_t)n * 64 + j] = __float2half(acc);
        }
    }
}

// ---------------- node transform -> fp16 tables, HFMA2 k-packed ----------------
// 256 threads; thread owns one output column of [Ts|Td]; 128-node tiles.
#define NT_TILE 128
__global__ __launch_bounds__(256) void nodetf_k(
    const float* __restrict__ gw, const float* __restrict__ cw,
    const float* __restrict__ gb, const float* __restrict__ cb) {
    __shared__ __half hs[NT_TILE * 64];  // [node][feat], row = 128B
    int c = threadIdx.x;
    const float* wbase;
    int cc, krow0;
    float bias = 0.f;
    if (c < 64)       { wbase = gw; cc = c;       krow0 = 0;  }
    else if (c < 128) { wbase = cw; cc = c - 64;  krow0 = 0;  }
    else if (c < 192) { wbase = gw; cc = c - 128; krow0 = 64; bias = gb[cc]; }
    else              { wbase = cw; cc = c - 192; krow0 = 64; bias = cb[cc]; }
    __half2 w2[32];
#pragma unroll
    for (int k2 = 0; k2 < 32; k2++)
        w2[k2] = __floats2half2_rn(wbase[(krow0 + 2 * k2) * 64 + cc],
                                   (2 * k2 + 1 < 64) ? wbase[(krow0 + 2 * k2 + 1) * 64 + cc] : 0.f);
    __half* tbl = (c < 128) ? (g_Tsh + c) : (g_Tdh + (c - 128));

    int n0 = blockIdx.x * NT_TILE;
    // load tile: NT_TILE*64 halfs = NT_TILE*8 uint4
#pragma unroll
    for (int i = 0; i < NT_TILE / 32; i++) {
        int idx = c + i * 256;
        int n = n0 + (idx >> 3);
        uint4 z = make_uint4(0u, 0u, 0u, 0u);
        ((uint4*)hs)[idx] = (n < NN) ? ((const uint4*)g_hh)[(size_t)n0 * 8 + idx] : z;
    }
    __syncthreads();

#pragma unroll 1
    for (int j0 = 0; j0 < NT_TILE; j0 += 4) {
        __half2 acc[4];
#pragma unroll
        for (int j = 0; j < 4; j++) acc[j] = __floats2half2_rn(0.f, 0.f);
#pragma unroll
        for (int k8 = 0; k8 < 8; k8++) {
#pragma unroll
            for (int j = 0; j < 4; j++) {
                // 16B = 8 halfs = 4 half2 pairs of consecutive k
                uint4 hv = ((const uint4*)(hs + (j0 + j) * 64))[k8];
                __half2 h0 = *(__half2*)&hv.x;
                __half2 h1 = *(__half2*)&hv.y;
                __half2 h2 = *(__half2*)&hv.z;
                __half2 h3 = *(__half2*)&hv.w;
                acc[j] = __hfma2(h0, w2[4 * k8 + 0], acc[j]);
                acc[j] = __hfma2(h1, w2[4 * k8 + 1], acc[j]);
                acc[j] = __hfma2(h2, w2[4 * k8 + 2], acc[j]);
                acc[j] = __hfma2(h3, w2[4 * k8 + 3], acc[j]);
            }
        }
#pragma unroll
        for (int j = 0; j < 4; j++) {
            int n = n0 + j0 + j;
            if (n < NN) {
                float2 f = __half22float2(acc[j]);
                tbl[(size_t)n * 128] = __float2half(f.x + f.y + bias);
            }
        }
    }
}

// ---------------- zero kernels ----------------
__global__ void zero_agg_k() {
    int i = blockIdx.x * 256 + threadIdx.x;
    if (i < NN * 16) ((float4*)g_agg)[i] = make_float4(0.f, 0.f, 0.f, 0.f);
    if (i < 128) g_stats[i] = 0.f;
}
__global__ void zero_pool_k() {
    int i = blockIdx.x * 256 + threadIdx.x;
    if (i < BB * 64) g_pool[i] = 0.f;
    if (i < BB) g_cnt[i] = 0.f;
}

// ---------------- edge pass: warp/edge, HFMA2 projection, smem ef ----------------
#define EPW 16  // edges per warp; block = 8 warps = 128 edges
__global__ __launch_bounds__(256, 4) void edge_k(
    const int* __restrict__ src, const int* __restrict__ dst,
    const float* __restrict__ ef,
    const float* __restrict__ gwE, const float* __restrict__ cwE) {
    __shared__ __half2 sef[128 * FE];  // per local edge, splatted ef value
    int tid = threadIdx.x;
    int warp = tid >> 5;
    int l = tid & 31;

    __half2 wgh[FE], wch[FE];
#pragma unroll
    for (int k = 0; k < FE; k++) {
        wgh[k] = __floats2half2_rn(gwE[k * 64 + 2 * l], gwE[k * 64 + 2 * l + 1]);
        wch[k] = __floats2half2_rn(cwE[k * 64 + 2 * l], cwE[k * 64 + 2 * l + 1]);
    }

    int base = blockIdx.x * 128;
    // stage ef: 128 edges x 10 floats, coalesced
#pragma unroll
    for (int i = tid; i < 128 * FE; i += 256) {
        float v = __ldcs(&ef[(size_t)base * FE + i]);
        sef[i] = __half2half2(__float2half(v));
    }
    __syncthreads();

    int le = warp * EPW;
#pragma unroll 1
    for (int it = 0; it < EPW; it++, le++) {
        int e = base + le;
        int s = __ldcs(&src[e]);
        int d = __ldcs(&dst[e]);
        const __half2* ts = (const __half2*)(g_Tsh + (size_t)s * 128);
        const __half2* td = (const __half2*)(g_Tdh + (size_t)d * 128);
        __half2 xh = __hadd2(ts[l], td[l]);
        __half2 yh = __hadd2(ts[32 + l], td[32 + l]);
#pragma unroll
        for (int k = 0; k < FE; k++) {
            __half2 ev = sef[le * FE + k];
            xh = __hfma2(ev, wgh[k], xh);
            yh = __hfma2(ev, wch[k], yh);
        }
        float2 xf = __half22float2(xh);
        float2 yf = __half22float2(yh);
        float m0 = fsigmoid(xf.x) * fsoftplus(yf.x);
        float m1 = fsigmoid(xf.y) * fsoftplus(yf.y);
        float p0 = __shfl_down_sync(0xffffffffu, m0, 1);
        float p1 = __shfl_down_sync(0xffffffffu, m1, 1);
        if ((l & 1) == 0)
            red_add_v4(g_agg + (size_t)s * 64 + 2 * l, m0, m1, p0, p1);
    }
}

// ---------------- BN stats ----------------
__global__ void stats_k() {
    int tid = threadIdx.x;
    int j = tid & 63;
    int r = tid >> 6;
    float s = 0.f, s2 = 0.f;
    for (int n = blockIdx.x * 4 + r; n < NN; n += gridDim.x * 4) {
        float v = g_agg[n * 64 + j];
        s += v;
        s2 += v * v;
    }
    __shared__ float sh[256], sh2[256];
    sh[tid] = s; sh2[tid] = s2;
    __syncthreads();
    if (tid < 64) {
        s = sh[tid] + sh[tid + 64] + sh[tid + 128] + sh[tid + 192];
        s2 = sh2[tid] + sh2[tid + 64] + sh2[tid + 128] + sh2[tid + 192];
        atomicAdd(&g_stats[tid], s);
        atomicAdd(&g_stats[64 + tid], s2);
    }
}

__global__ void bnfin_k(const float* __restrict__ bg, const float* __restrict__ bb) {
    int j = threadIdx.x;
    float mean = g_stats[j] * (1.f / NN);
    float var = g_stats[64 + j] * (1.f / NN) - mean * mean;
    float sc = bg[j] * rsqrtf(fmaxf(var, 0.f) + 1e-5f);
    g_scale[j] = sc;
    g_shift[j] = bb[j] - mean * sc;
}

// ---------------- h = softplus(h + agg*scale + shift), also fp16 copy --------
__global__ void upd_k() {
    int i = blockIdx.x * 256 + threadIdx.x;
    if (i >= NN * 16) return;
    int j4 = (i & 15) * 4;
    float4 a = ((const float4*)g_agg)[i];
    float4 h = ((const float4*)g_h)[i];
    float4 sc = *(const float4*)(g_scale + j4);
    float4 sf = *(const float4*)(g_shift + j4);
    h.x = fsoftplus(fmaf(a.x, sc.x, h.x + sf.x));
    h.y = fsoftplus(fmaf(a.y, sc.y, h.y + sf.y));
    h.z = fsoftplus(fmaf(a.z, sc.z, h.z + sf.z));
    h.w = fsoftplus(fmaf(a.w, sc.w, h.w + sf.w));
    ((float4*)g_h)[i] = h;
    __half2 h01 = __floats2half2_rn(h.x, h.y);
    __half2 h23 = __floats2half2_rn(h.z, h.w);
    uint2 packed;
    packed.x = *(unsigned*)&h01;
    packed.y = *(unsigned*)&h23;
    ((uint2*)g_hh)[i] = packed;
}

// ---------------- pooling ----------------
__global__ void pool_k(const int* __restrict__ gi) {
    int i = blockIdx.x * 256 + threadIdx.x;
    if (i >= NN * 16) return;
    int n = i >> 4;
    int q = i & 15;
    int g = gi[n];
    float4 v = ((const float4*)g_h)[i];
    red_add_v4(g_pool + g * 64 + 4 * q, v.x, v.y, v.z, v.w);
    if (q == 0) red_add_f(&g_cnt[g], 1.f);
}

// ---------------- final MLP, one block per graph ----------------
__global__ void mlp_k(const float* __restrict__ w1, const float* __restrict__ b1,
                      const float* __restrict__ w2, const float* __restrict__ b2,
                      const float* __restrict__ w3, const float* __restrict__ b3,
                      float* __restrict__ out) {
    int b = blockIdx.x;
    int t = threadIdx.x;  // 128 threads
    __shared__ float pm[64];
    __shared__ float s1[128];
    __shared__ float s2[64];
    __shared__ float red[128];
    if (t < 64) {
        float c = g_cnt[b];
        c = (c < 1.f) ? 1.f : c;
        pm[t] = g_pool[b * 64 + t] / c;
    }
    __syncthreads();
    float a = b1[t];
#pragma unroll
    for (int k = 0; k < 64; k++) a = fmaf(pm[k], w1[k * 128 + t], a);
    s1[t] = fsoftplus(a);
    __syncthreads();
    if (t < 64) {
        float a2 = b2[t];
#pragma unroll
        for (int k = 0; k < 128; k++) a2 = fmaf(s1[k], w2[k * 64 + t], a2);
        s2[t] = fsoftplus(a2);
    }
    __syncthreads();
    float p = (t < 64) ? s2[t] * w3[t] : 0.f;
    red[t] = p;
    __syncthreads();
#pragma unroll
    for (int off = 64; off > 0; off >>= 1) {
        if (t < off) red[t] += red[t + off];
        __syncthreads();
    }
    if (t == 0) out[b] = red[0] + b3[0];
}

extern "C" void kernel_launch(void* const* d_in, const int* in_sizes, int n_in,
                              void* d_out, int out_size) {
    const float* nf  = (const float*)d_in[0];
    const int*   ei  = (const int*)d_in[1];
    const float* ef  = (const float*)d_in[2];
    const int*   gi  = (const int*)d_in[3];
    const float* ew  = (const float*)d_in[4];
    const float* eb  = (const float*)d_in[5];
    const float* gw  = (const float*)d_in[6];
    const float* gb  = (const float*)d_in[7];
    const float* cw  = (const float*)d_in[8];
    const float* cb  = (const float*)d_in[9];
    const float* bng = (const float*)d_in[10];
    const float* bnb = (const float*)d_in[11];
    const float* w1  = (const float*)d_in[12];
    const float* b1  = (const float*)d_in[13];
    const float* w2  = (const float*)d_in[14];
    const float* b2  = (const float*)d_in[15];
    const float* w3  = (const float*)d_in[16];
    const float* b3  = (const float*)d_in[17];
    float* out = (float*)d_out;
    const int* srcI = ei;
    const int* dstI = ei + EE;

    embed_k<<<(NN + 31) / 32, 256>>>(nf, ew, eb);
    for (int i = 0; i < 3; i++) {
        const float* gwi = gw + i * 138 * 64;
        const float* cwi = cw + i * 138 * 64;
        nodetf_k<<<(NN + NT_TILE - 1) / NT_TILE, 256>>>(gwi, cwi, gb + i * 64, cb + i * 64);
        zero_agg_k<<<(NN * 16 + 255) / 256, 256>>>();
        edge_k<<<EE / 128, 256>>>(srcI, dstI, ef, gwi + 128 * 64, cwi + 128 * 64);
        stats_k<<<512, 256>>>();
        bnfin_k<<<1, 64>>>(bng + i * 64, bnb + i * 64);
        upd_k<<<(NN * 16 + 255) / 256, 256>>>();
    }
    zero_pool_k<<<64, 256>>>();
    pool_k<<<(NN * 16 + 255) / 256, 256>>>(gi);
    mlp_k<<<BB, 128>>>(w1, b1, w2, b2, w3, b3, out);
}